// round 1
// baseline (speedup 1.0000x reference)
#include <cuda_runtime.h>
#include <cstdint>

#define NN   500000
#define FD   128
#define IN0  144
#define NG   2048
#define EPSV 1e-5f
#define TM   64
#define WST  130          // padded shared stride for transposed weights / h tile
#define XST  148          // padded shared stride for x0 tile

typedef unsigned long long ull;

// ---------------- scratch (static device globals; no allocation at runtime) ----
__device__ __align__(16) float g_z[(size_t)NN * FD];      // 256 MB: z = h @ g2w^T
__device__ __align__(16) float g_pt[(size_t)NN * 16];     // 32 MB: transposed pers0
__device__ __align__(16) float g_xsum[NG * IN0];
__device__ __align__(16) float g_cnt[NG];
__device__ __align__(16) float g_c1[NG * FD];
__device__ __align__(16) float g_c2[NG * FD];
__device__ __align__(16) float g_hsum[NG * FD];
__device__ __align__(16) int   g_start[NG + 1];
__device__ __align__(16) float g_colsum[FD];
__device__ __align__(16) float g_colsq[FD];
__device__ __align__(16) float g_scale[FD];
__device__ __align__(16) float g_shift[FD];

// ---------------- f32x2 helpers ----------------
__device__ __forceinline__ ull pack2(float lo, float hi) {
    ull r;
    asm("mov.b64 %0, {%1,%2};" : "=l"(r) : "f"(lo), "f"(hi));
    return r;
}
__device__ __forceinline__ void unpack2(ull v, float& lo, float& hi) {
    asm("mov.b64 {%0,%1}, %2;" : "=f"(lo), "=f"(hi) : "l"(v));
}
__device__ __forceinline__ ull ffma2(ull a, ull b, ull c) {
    ull d;
    asm("fma.rn.f32x2 %0, %1, %2, %3;" : "=l"(d) : "l"(a), "l"(b), "l"(c));
    return d;
}

// ---------------- K0: zero accumulators, init segment starts ----------------
__global__ void k_init() {
    int i = blockIdx.x * blockDim.x + threadIdx.x;
    if (i < NG * FD) g_hsum[i] = 0.f;
    if (i < FD) { g_colsum[i] = 0.f; g_colsq[i] = 0.f; }
    if (i <= NG) g_start[i] = NN;
}

// ---------------- K0b: transpose pers0 [8][N][2] -> g_pt [N][16] ----------------
__global__ void k_tr(const float2* __restrict__ p0) {
    __shared__ float sh[32 * 18];
    int t = threadIdx.x;
    int n0 = blockIdx.x * 32;
    int p = t >> 5, lane = t & 31;
    int n = n0 + lane;
    if (n < NN) {
        float2 v = p0[(size_t)p * NN + n];
        sh[lane * 18 + 2 * p]     = v.x;
        sh[lane * 18 + 2 * p + 1] = v.y;
    }
    __syncthreads();
    for (int idx = t; idx < 512; idx += 256) {
        int r = idx >> 4, c = idx & 15;
        int nn = n0 + r;
        if (nn < NN) g_pt[(size_t)nn * 16 + c] = sh[r * 18 + c];
    }
}

// ---------------- K0c: segment boundaries (batch is sorted) ----------------
__global__ void k_bounds(const int* __restrict__ batch) {
    int n = blockIdx.x * blockDim.x + threadIdx.x;
    if (n >= NN) return;
    int b = batch[n];
    int prev = (n == 0) ? -1 : batch[n - 1];
    for (int g = prev + 1; g <= b; g++) g_start[g] = n;
}

// ---------------- K1: per-segment column sums of x0 (contiguous; no atomics) ---
__global__ void k_segsum(const float* __restrict__ x) {
    int g = blockIdx.x, t = threadIdx.x;
    int s = g_start[g], e = g_start[g + 1];
    if (t < IN0) {
        float acc = 0.f;
        if (t < FD) {
            for (int n = s; n < e; n++) acc += x[(size_t)n * FD + t];
        } else {
            int c = t - FD;
            for (int n = s; n < e; n++) acc += g_pt[(size_t)n * 16 + c];
        }
        g_xsum[g * IN0 + t] = acc;
    }
    if (t == 0) g_cnt[g] = (float)(e - s);
}

// ---------------- K2/K4: c = gb - (sum/cnt) @ lw^T  (per-graph correction) -----
// which==0: g_xsum -> g_c1 (K=144);  which==1: g_hsum -> g_c2 (K=128)
__global__ void k_corr(int which, const float* __restrict__ lw,
                       const float* __restrict__ gb, int K, int padK) {
    extern __shared__ float dsm[];
    float* shw = dsm;              // FD * padK
    float* shm = dsm + FD * padK;  // K
    const float* msum = which ? g_hsum : g_xsum;
    float* cout       = which ? g_c2   : g_c1;
    int t = threadIdx.x;
    for (int idx = t; idx < FD * K; idx += FD) {
        int j = idx / K;
        int k = idx - j * K;
        shw[j * padK + k] = lw[idx];
    }
    float gbv = gb[t];
    for (int gg = 0; gg < 16; gg++) {
        int g = blockIdx.x * 16 + gg;
        float inv = 1.f / fmaxf(g_cnt[g], 1.f);
        __syncthreads();
        for (int k = t; k < K; k += FD) shm[k] = msum[g * K + k] * inv;
        __syncthreads();
        float acc = 0.f;
        #pragma unroll 4
        for (int k = 0; k < K; k++) acc += shm[k] * shw[t * padK + k];
        cout[g * FD + t] = gbv - acc;
    }
}

// ---------------- K3: persistent fused  h=relu(x0@W1^T+c1); hsum; z=h@W2^T -----
__global__ __launch_bounds__(256, 1)
void k_main(const float* __restrict__ x, const int* __restrict__ batch,
            const float* __restrict__ g1w, const float* __restrict__ g2w) {
    extern __shared__ float dsm[];
    float* sw1 = dsm;                   // IN0 * WST  (transposed: [k][j])
    float* sw2 = sw1 + IN0 * WST;       // FD * WST
    float* sx  = sw2 + FD * WST;        // TM * XST (x0), reused as h with stride WST
    int*   sb  = (int*)(sx + TM * XST); // TM

    int t = threadIdx.x;
    // load weights transposed (coalesced global reads, 2-way smem store conflicts)
    for (int idx = t; idx < FD * IN0; idx += 256) {
        int j = idx / IN0;
        int k = idx - j * IN0;
        sw1[k * WST + j] = g1w[idx];
    }
    for (int idx = t; idx < FD * FD; idx += 256) {
        int j = idx >> 7;
        int k = idx & 127;
        sw2[k * WST + j] = g2w[idx];
    }

    int tx = t & 15, ty = t >> 4;
    int cb = tx << 1;                    // thread columns: cb + 32*m, m=0..3 (pairs)
    const int NT = (NN + TM - 1) / TM;

    for (int tile = blockIdx.x; tile < NT; tile += gridDim.x) {
        int n0 = tile * TM;
        __syncthreads();  // previous tile's readers done before overwriting sx
        for (int idx = t; idx < TM * FD; idx += 256) {
            int r = idx >> 7, c = idx & 127;
            int n = n0 + r;
            sx[r * XST + c] = (n < NN) ? x[(size_t)n * FD + c] : 0.f;
        }
        for (int idx = t; idx < TM * 16; idx += 256) {
            int r = idx >> 4, c = idx & 15;
            int n = n0 + r;
            sx[r * XST + FD + c] = (n < NN) ? g_pt[(size_t)n * 16 + c] : 0.f;
        }
        if (t < TM) {
            int n = n0 + t;
            sb[t] = (n < NN) ? batch[n] : -1;
        }
        __syncthreads();

        // ---- GEMM1: acc[i][m] over k in [0,144) ----
        ull a0[4], a1[4], a2[4], a3[4];
        #pragma unroll
        for (int i = 0; i < 4; i++) { a0[i] = 0ull; a1[i] = 0ull; a2[i] = 0ull; a3[i] = 0ull; }
        #pragma unroll 2
        for (int k = 0; k < IN0; k += 2) {
            float2 xv[4];
            #pragma unroll
            for (int i = 0; i < 4; i++)
                xv[i] = *(const float2*)(sx + (ty + 16 * i) * XST + k);
            #pragma unroll
            for (int kk = 0; kk < 2; kk++) {
                const float* wb = sw1 + (k + kk) * WST + cb;
                ull b0 = *(const ull*)(wb);
                ull b1 = *(const ull*)(wb + 32);
                ull b2 = *(const ull*)(wb + 64);
                ull b3 = *(const ull*)(wb + 96);
                #pragma unroll
                for (int i = 0; i < 4; i++) {
                    float xs = kk ? xv[i].y : xv[i].x;
                    ull xx = pack2(xs, xs);
                    a0[i] = ffma2(xx, b0, a0[i]);
                    a1[i] = ffma2(xx, b1, a1[i]);
                    a2[i] = ffma2(xx, b2, a2[i]);
                    a3[i] = ffma2(xx, b3, a3[i]);
                }
            }
        }
        __syncthreads();  // all GEMM1 reads of sx done

        // ---- epilogue: h = relu(acc + c1[batch]); store into sx (stride WST) ----
        #pragma unroll
        for (int i = 0; i < 4; i++) {
            int r = ty + 16 * i;
            int g = sb[r];
            float2 c0 = {0.f, 0.f}, c1v = {0.f, 0.f}, c2v = {0.f, 0.f}, c3v = {0.f, 0.f};
            if (g >= 0) {
                const float* cp = g_c1 + g * FD + cb;
                c0  = *(const float2*)(cp);
                c1v = *(const float2*)(cp + 32);
                c2v = *(const float2*)(cp + 64);
                c3v = *(const float2*)(cp + 96);
            }
            float h0, h1;
            float* hp = sx + r * WST + cb;
            unpack2(a0[i], h0, h1);
            *(float2*)(hp)      = make_float2(fmaxf(h0 + c0.x, 0.f),  fmaxf(h1 + c0.y, 0.f));
            unpack2(a1[i], h0, h1);
            *(float2*)(hp + 32) = make_float2(fmaxf(h0 + c1v.x, 0.f), fmaxf(h1 + c1v.y, 0.f));
            unpack2(a2[i], h0, h1);
            *(float2*)(hp + 64) = make_float2(fmaxf(h0 + c2v.x, 0.f), fmaxf(h1 + c2v.y, 0.f));
            unpack2(a3[i], h0, h1);
            *(float2*)(hp + 96) = make_float2(fmaxf(h0 + c3v.x, 0.f), fmaxf(h1 + c3v.y, 0.f));
        }
        __syncthreads();  // h tile complete

        // ---- segment sums of h (batch sorted: run-length, few atomics) ----
        {
            int c = t & 127;
            int rb = (t >> 7) * 32;
            float run = 0.f;
            int gc = -1;
            for (int r = rb; r < rb + 32; r++) {
                int g = sb[r];
                if (g != gc) {
                    if (gc >= 0) atomicAdd(&g_hsum[gc * FD + c], run);
                    run = 0.f;
                    gc = g;
                }
                if (g >= 0) run += sx[r * WST + c];
            }
            if (gc >= 0) atomicAdd(&g_hsum[gc * FD + c], run);
        }

        // ---- GEMM2: z = h @ W2^T ----
        #pragma unroll
        for (int i = 0; i < 4; i++) { a0[i] = 0ull; a1[i] = 0ull; a2[i] = 0ull; a3[i] = 0ull; }
        #pragma unroll 2
        for (int k = 0; k < FD; k += 2) {
            float2 xv[4];
            #pragma unroll
            for (int i = 0; i < 4; i++)
                xv[i] = *(const float2*)(sx + (ty + 16 * i) * WST + k);
            #pragma unroll
            for (int kk = 0; kk < 2; kk++) {
                const float* wb = sw2 + (k + kk) * WST + cb;
                ull b0 = *(const ull*)(wb);
                ull b1 = *(const ull*)(wb + 32);
                ull b2 = *(const ull*)(wb + 64);
                ull b3 = *(const ull*)(wb + 96);
                #pragma unroll
                for (int i = 0; i < 4; i++) {
                    float xs = kk ? xv[i].y : xv[i].x;
                    ull xx = pack2(xs, xs);
                    a0[i] = ffma2(xx, b0, a0[i]);
                    a1[i] = ffma2(xx, b1, a1[i]);
                    a2[i] = ffma2(xx, b2, a2[i]);
                    a3[i] = ffma2(xx, b3, a3[i]);
                }
            }
        }
        // ---- store z ----
        #pragma unroll
        for (int i = 0; i < 4; i++) {
            int r = ty + 16 * i;
            int n = n0 + r;
            if (n < NN) {
                float* zp = g_z + (size_t)n * FD + cb;
                float v0, v1;
                unpack2(a0[i], v0, v1); *(float2*)(zp)      = make_float2(v0, v1);
                unpack2(a1[i], v0, v1); *(float2*)(zp + 32) = make_float2(v0, v1);
                unpack2(a2[i], v0, v1); *(float2*)(zp + 64) = make_float2(v0, v1);
                unpack2(a3[i], v0, v1); *(float2*)(zp + 96) = make_float2(v0, v1);
            }
        }
    }
}

// ---------------- K5: BN statistics of y = z + c2[batch] ----------------
__global__ void k_stats(const int* __restrict__ batch) {
    __shared__ float red[256];
    int t = threadIdx.x;
    int c = t & 127;
    const int RPB = (NN + 1023) / 1024;
    int r0 = blockIdx.x * RPB;
    int r1 = min(r0 + RPB, NN);
    float s = 0.f, q = 0.f;
    for (int r = r0 + (t >> 7); r < r1; r += 2) {
        int g = batch[r];
        float v = g_z[(size_t)r * FD + c] + g_c2[g * FD + c];
        s += v;
        q += v * v;
    }
    red[t] = s;
    __syncthreads();
    if (t < 128) atomicAdd(&g_colsum[c], red[t] + red[t + 128]);
    __syncthreads();
    red[t] = q;
    __syncthreads();
    if (t < 128) atomicAdd(&g_colsq[c], red[t] + red[t + 128]);
}

// ---------------- K5b: finalize BN scale/shift ----------------
__global__ void k_fin(const float* __restrict__ bng, const float* __restrict__ bnb) {
    int c = threadIdx.x;
    float mu  = g_colsum[c] / (float)NN;
    float var = g_colsq[c] / (float)NN - mu * mu;
    float inv = rsqrtf(var + EPSV);
    float sc  = bng[c] * inv;
    g_scale[c] = sc;
    g_shift[c] = bnb[c] - mu * sc;
}

// ---------------- K6: out = x + (z + c2[batch]) * scale + shift ----------------
__global__ void k_out(const float* __restrict__ x, const int* __restrict__ batch,
                      float* __restrict__ out) {
    int idx = blockIdx.x * blockDim.x + threadIdx.x;  // over NN*32 float4 groups
    if (idx >= NN * 32) return;
    int n = idx >> 5;
    int qd = idx & 31;
    int c0 = qd << 2;
    int g = batch[n];
    float4 zv = *(const float4*)(g_z + (size_t)n * FD + c0);
    float4 xv = *(const float4*)(x + (size_t)n * FD + c0);
    float4 cv = *(const float4*)(g_c2 + g * FD + c0);
    float4 sc = *(const float4*)(g_scale + c0);
    float4 sh = *(const float4*)(g_shift + c0);
    float4 o;
    o.x = xv.x + (zv.x + cv.x) * sc.x + sh.x;
    o.y = xv.y + (zv.y + cv.y) * sc.y + sh.y;
    o.z = xv.z + (zv.z + cv.z) * sc.z + sh.z;
    o.w = xv.w + (zv.w + cv.w) * sc.w + sh.w;
    ((float4*)out)[idx] = o;
}

// ---------------- host ----------------
extern "C" void kernel_launch(void* const* d_in, const int* in_sizes, int n_in,
                              void* d_out, int out_size) {
    const float* x     = (const float*)d_in[0];
    const int*   batch = (const int*)d_in[1];
    const float* pers0 = (const float*)d_in[2];
    const float* g1w   = (const float*)d_in[3];
    const float* g1b   = (const float*)d_in[4];
    const float* l1w   = (const float*)d_in[5];
    const float* g2w   = (const float*)d_in[6];
    const float* g2b   = (const float*)d_in[7];
    const float* l2w   = (const float*)d_in[8];
    const float* bng   = (const float*)d_in[9];
    const float* bnb   = (const float*)d_in[10];
    float* out = (float*)d_out;

    const int smem_main  = (IN0 * WST + FD * WST + TM * XST) * 4 + TM * 4;  // 179,584 B
    const int smem_corr1 = (FD * 145 + IN0) * 4;                            // 74,816 B
    const int smem_corr2 = (FD * 129 + FD) * 4;                             // 66,560 B
    cudaFuncSetAttribute(k_main, cudaFuncAttributeMaxDynamicSharedMemorySize, smem_main);
    cudaFuncSetAttribute(k_corr, cudaFuncAttributeMaxDynamicSharedMemorySize, smem_corr1);

    k_init<<<(NG * FD + 255) / 256, 256>>>();
    k_tr<<<(NN + 31) / 32, 256>>>((const float2*)pers0);
    k_bounds<<<(NN + 255) / 256, 256>>>(batch);
    k_segsum<<<NG, 160>>>(x);
    k_corr<<<NG / 16, 128, smem_corr1>>>(0, l1w, g1b, IN0, 145);
    k_main<<<304, 256, smem_main>>>(x, batch, g1w, g2w);
    k_corr<<<NG / 16, 128, smem_corr2>>>(1, l2w, g2b, FD, 129);
    k_stats<<<1024, 256>>>(batch);
    k_fin<<<1, 128>>>(bng, bnb);
    k_out<<<(NN * 32 + 255) / 256, 256>>>(x, batch, out);
}

// round 2
// speedup vs baseline: 1.0889x; 1.0889x over previous
#include <cuda_runtime.h>
#include <cstdint>

#define NN   500000
#define FD   128
#define IN0  144
#define NG   2048
#define EPSV 1e-5f
#define TM   128
#define WST  132          // padded stride (weights / h / z tiles), 16B-aligned
#define XST  148          // padded stride for x0 tile

typedef unsigned long long ull;

// ---------------- scratch (static device globals) ----------------
__device__ __align__(16) float g_z[(size_t)NN * FD];      // 256 MB
__device__ __align__(16) float g_pt[(size_t)NN * 16];     // 32 MB transposed pers0
__device__ __align__(16) float g_xsum[NG * IN0];
__device__ __align__(16) float g_cnt[NG];
__device__ __align__(16) float g_c1[NG * FD];
__device__ __align__(16) float g_c2[NG * FD];
__device__ __align__(16) float g_hsum[NG * FD];
__device__ __align__(16) float g_zsum[NG * FD];
__device__ __align__(16) int   g_start[NG + 1];
__device__ __align__(16) float g_colsum[FD];
__device__ __align__(16) float g_colsq[FD];
__device__ __align__(16) float g_scale[FD];
__device__ __align__(16) float g_shift[FD];

// ---------------- f32x2 helpers ----------------
__device__ __forceinline__ ull pack2(float lo, float hi) {
    ull r;
    asm("mov.b64 %0, {%1,%2};" : "=l"(r) : "f"(lo), "f"(hi));
    return r;
}
__device__ __forceinline__ void unpack2(ull v, float& lo, float& hi) {
    asm("mov.b64 {%0,%1}, %2;" : "=f"(lo), "=f"(hi) : "l"(v));
}
__device__ __forceinline__ ull ffma2(ull a, ull b, ull c) {
    ull d;
    asm("fma.rn.f32x2 %0, %1, %2, %3;" : "=l"(d) : "l"(a), "l"(b), "l"(c));
    return d;
}

// ---------------- K0: zero accumulators, init segment starts ----------------
__global__ void k_init() {
    int i = blockIdx.x * blockDim.x + threadIdx.x;
    if (i < NG * FD) { g_hsum[i] = 0.f; g_zsum[i] = 0.f; }
    if (i < FD) { g_colsum[i] = 0.f; g_colsq[i] = 0.f; }
    if (i <= NG) g_start[i] = NN;
}

// ---------------- K0b: transpose pers0 [8][N][2] -> g_pt [N][16] -------------
__global__ void k_tr(const float2* __restrict__ p0) {
    __shared__ float sh[32 * 18];
    int t = threadIdx.x;
    int n0 = blockIdx.x * 32;
    int p = t >> 5, lane = t & 31;
    int n = n0 + lane;
    if (n < NN) {
        float2 v = p0[(size_t)p * NN + n];
        sh[lane * 18 + 2 * p]     = v.x;
        sh[lane * 18 + 2 * p + 1] = v.y;
    }
    __syncthreads();
    for (int idx = t; idx < 512; idx += 256) {
        int r = idx >> 4, c = idx & 15;
        int nn = n0 + r;
        if (nn < NN) g_pt[(size_t)nn * 16 + c] = sh[r * 18 + c];
    }
}

// ---------------- K0c: segment boundaries (batch sorted) ----------------
__global__ void k_bounds(const int* __restrict__ batch) {
    int n = blockIdx.x * blockDim.x + threadIdx.x;
    if (n >= NN) return;
    int b = batch[n];
    int prev = (n == 0) ? -1 : batch[n - 1];
    for (int g = prev + 1; g <= b; g++) g_start[g] = n;
}

// ---------------- K1: per-segment column sums of x0 (no atomics) -------------
__global__ void k_segsum(const float* __restrict__ x) {
    __shared__ float sh[384];
    int g = blockIdx.x, t = threadIdx.x;
    int s = g_start[g], e = g_start[g + 1];
    float acc = 0.f;
    if (t < 256) {
        int c = t & 127;
        #pragma unroll 4
        for (int n = s + (t >> 7); n < e; n += 2) acc += x[(size_t)n * FD + c];
    } else {
        int u = t - 256;
        int c = u & 15;
        #pragma unroll 2
        for (int n = s + (u >> 4); n < e; n += 8) acc += g_pt[(size_t)n * 16 + c];
    }
    sh[t] = acc;
    __syncthreads();
    if (t < 128) {
        g_xsum[g * IN0 + t] = sh[t] + sh[t + 128];
    } else if (t < 144) {
        int c = t - 128;
        float a = 0.f;
        #pragma unroll
        for (int j = 0; j < 8; j++) a += sh[256 + j * 16 + c];
        g_xsum[g * IN0 + t] = a;
    }
    if (t == 0) g_cnt[g] = (float)(e - s);
}

// ---------------- K2/K4: c = gb - (sum/cnt) @ lw^T ----------------
__global__ void k_corr(int which, const float* __restrict__ lw,
                       const float* __restrict__ gb, int K, int padK) {
    extern __shared__ float dsm[];
    float* shw = dsm;              // FD * padK
    float* shm = dsm + FD * padK;  // K
    const float* msum = which ? g_hsum : g_xsum;
    float* cout       = which ? g_c2   : g_c1;
    int t = threadIdx.x;
    for (int idx = t; idx < FD * K; idx += FD) {
        int j = idx / K;
        int k = idx - j * K;
        shw[j * padK + k] = lw[idx];
    }
    float gbv = gb[t];
    for (int gg = 0; gg < 16; gg++) {
        int g = blockIdx.x * 16 + gg;
        float inv = 1.f / fmaxf(g_cnt[g], 1.f);
        __syncthreads();
        for (int k = t; k < K; k += FD) shm[k] = msum[g * K + k] * inv;
        __syncthreads();
        float acc = 0.f;
        #pragma unroll 4
        for (int k = 0; k < K; k++) acc += shm[k] * shw[t * padK + k];
        cout[g * FD + t] = gbv - acc;
    }
}

// ---------------- GEMM inner: 8 rows x 8 cols per thread ----------------
template <int K, int AS>
__device__ __forceinline__ void gemm_acc(const float* __restrict__ a_base,
                                         const float* __restrict__ w,
                                         int tx, int ty, ull acc[8][4]) {
    #pragma unroll
    for (int i = 0; i < 8; i++)
        #pragma unroll
        for (int j = 0; j < 4; j++) acc[i][j] = 0ull;
    #pragma unroll 2
    for (int k = 0; k < K; k += 2) {
        float2 xv[8];
        #pragma unroll
        for (int i = 0; i < 8; i++)
            xv[i] = *(const float2*)(a_base + (ty + 16 * i) * AS + k);
        #pragma unroll
        for (int kk = 0; kk < 2; kk++) {
            const float* wb = w + (k + kk) * WST + (tx << 3);
            ulonglong2 b01 = *(const ulonglong2*)(wb);
            ulonglong2 b23 = *(const ulonglong2*)(wb + 4);
            #pragma unroll
            for (int i = 0; i < 8; i++) {
                float xs = kk ? xv[i].y : xv[i].x;
                ull xx = pack2(xs, xs);
                acc[i][0] = ffma2(xx, b01.x, acc[i][0]);
                acc[i][1] = ffma2(xx, b01.y, acc[i][1]);
                acc[i][2] = ffma2(xx, b23.x, acc[i][2]);
                acc[i][3] = ffma2(xx, b23.y, acc[i][3]);
            }
        }
    }
}

// ---------------- K3: persistent fused main kernel ----------------
__global__ __launch_bounds__(256, 1)
void k_main(const float* __restrict__ x, const int* __restrict__ batch,
            const float* __restrict__ g1w, const float* __restrict__ g2w) {
    extern __shared__ float dsm[];
    float* sw1 = dsm;                   // IN0 * WST (transposed: [k][j])
    float* sw2 = sw1 + IN0 * WST;       // FD * WST
    float* sx  = sw2 + FD * WST;        // TM * XST (x0) reused stride WST for h/z
    int*   sb  = (int*)(sx + TM * XST); // TM

    int t = threadIdx.x;
    for (int idx = t; idx < FD * IN0; idx += 256) {
        int j = idx / IN0;
        int k = idx - j * IN0;
        sw1[k * WST + j] = g1w[idx];
    }
    for (int idx = t; idx < FD * FD; idx += 256) {
        int j = idx >> 7;
        int k = idx & 127;
        sw2[k * WST + j] = g2w[idx];
    }

    int tx = t & 15, ty = t >> 4;
    int c0 = tx << 3;                 // 8 consecutive columns per thread
    float csum[8], csq[8];
    #pragma unroll
    for (int j = 0; j < 8; j++) { csum[j] = 0.f; csq[j] = 0.f; }

    const int NT = (NN + TM - 1) / TM;
    ull acc[8][4];

    for (int tile = blockIdx.x; tile < NT; tile += gridDim.x) {
        int n0 = tile * TM;
        __syncthreads();  // prior tile's smem readers done
        // load x tile (128x128 via float4) + pt (128x16)
        for (int idx = t; idx < TM * 32; idx += 256) {
            int r = idx >> 5, q = idx & 31;
            int n = n0 + r;
            float4 v = (n < NN) ? *(const float4*)(x + (size_t)n * FD + q * 4)
                                : make_float4(0.f, 0.f, 0.f, 0.f);
            *(float4*)(sx + r * XST + q * 4) = v;
        }
        for (int idx = t; idx < TM * 4; idx += 256) {
            int r = idx >> 2, q = idx & 3;
            int n = n0 + r;
            float4 v = (n < NN) ? *(const float4*)(g_pt + (size_t)n * 16 + q * 4)
                                : make_float4(0.f, 0.f, 0.f, 0.f);
            *(float4*)(sx + r * XST + FD + q * 4) = v;
        }
        if (t < TM) {
            int n = n0 + t;
            sb[t] = (n < NN) ? batch[n] : -1;
        }
        __syncthreads();

        // ---- GEMM1 ----
        gemm_acc<IN0, XST>(sx, sw1, tx, ty, acc);
        __syncthreads();  // GEMM1 reads of sx done

        // ---- epilogue 1: h = relu(acc + c1[batch]) into sx (stride WST) ----
        #pragma unroll
        for (int i = 0; i < 8; i++) {
            int r = ty + 16 * i;
            int g = sb[r];
            float4 cA = make_float4(0.f, 0.f, 0.f, 0.f);
            float4 cB = cA;
            if (g >= 0) {
                cA = *(const float4*)(g_c1 + g * FD + c0);
                cB = *(const float4*)(g_c1 + g * FD + c0 + 4);
            }
            float h0, h1, h2, h3, h4, h5, h6, h7;
            unpack2(acc[i][0], h0, h1); unpack2(acc[i][1], h2, h3);
            unpack2(acc[i][2], h4, h5); unpack2(acc[i][3], h6, h7);
            float* hp = sx + r * WST + c0;
            *(float4*)(hp)     = make_float4(fmaxf(h0 + cA.x, 0.f), fmaxf(h1 + cA.y, 0.f),
                                             fmaxf(h2 + cA.z, 0.f), fmaxf(h3 + cA.w, 0.f));
            *(float4*)(hp + 4) = make_float4(fmaxf(h4 + cB.x, 0.f), fmaxf(h5 + cB.y, 0.f),
                                             fmaxf(h6 + cB.z, 0.f), fmaxf(h7 + cB.w, 0.f));
        }
        __syncthreads();  // h tile ready

        // ---- hsum (run-length, batch sorted) ----
        {
            int c = t & 127;
            int rb = (t >> 7) * 64;
            float run = 0.f;
            int gc = -1;
            for (int r = rb; r < rb + 64; r++) {
                int g = sb[r];
                if (g != gc) {
                    if (gc >= 0) atomicAdd(&g_hsum[gc * FD + c], run);
                    run = 0.f;
                    gc = g;
                }
                if (g >= 0) run += sx[r * WST + c];
            }
            if (gc >= 0) atomicAdd(&g_hsum[gc * FD + c], run);
        }

        // ---- GEMM2 ----
        gemm_acc<FD, WST>(sx, sw2, tx, ty, acc);

        // ---- epilogue 2: z -> gmem + column stats in regs ----
        float zv[8][8];
        #pragma unroll
        for (int i = 0; i < 8; i++) {
            unpack2(acc[i][0], zv[i][0], zv[i][1]);
            unpack2(acc[i][1], zv[i][2], zv[i][3]);
            unpack2(acc[i][2], zv[i][4], zv[i][5]);
            unpack2(acc[i][3], zv[i][6], zv[i][7]);
            int r = ty + 16 * i;
            int n = n0 + r;
            if (n < NN) {
                float* zp = g_z + (size_t)n * FD + c0;
                *(float4*)(zp)     = make_float4(zv[i][0], zv[i][1], zv[i][2], zv[i][3]);
                *(float4*)(zp + 4) = make_float4(zv[i][4], zv[i][5], zv[i][6], zv[i][7]);
                #pragma unroll
                for (int j = 0; j < 8; j++) {
                    csum[j] += zv[i][j];
                    csq[j]  += zv[i][j] * zv[i][j];
                }
            }
        }
        __syncthreads();  // all GEMM2 reads of h done before overwrite

        // ---- z into smem for per-graph zsum ----
        #pragma unroll
        for (int i = 0; i < 8; i++) {
            int r = ty + 16 * i;
            float* zp = sx + r * WST + c0;
            *(float4*)(zp)     = make_float4(zv[i][0], zv[i][1], zv[i][2], zv[i][3]);
            *(float4*)(zp + 4) = make_float4(zv[i][4], zv[i][5], zv[i][6], zv[i][7]);
        }
        __syncthreads();

        // ---- zsum (run-length) ----
        {
            int c = t & 127;
            int rb = (t >> 7) * 64;
            float run = 0.f;
            int gc = -1;
            for (int r = rb; r < rb + 64; r++) {
                int g = sb[r];
                if (g != gc) {
                    if (gc >= 0) atomicAdd(&g_zsum[gc * FD + c], run);
                    run = 0.f;
                    gc = g;
                }
                if (g >= 0) run += sx[r * WST + c];
            }
            if (gc >= 0) atomicAdd(&g_zsum[gc * FD + c], run);
        }
    }

    // ---- final block reduction of column stats ----
    __syncthreads();
    float* red = sx;  // reuse
    #pragma unroll 1
    for (int j = 0; j < 8; j++) {
        red[t] = csum[j];
        __syncthreads();
        if (ty == 0) {
            float s = 0.f;
            #pragma unroll
            for (int yy = 0; yy < 16; yy++) s += red[yy * 16 + tx];
            atomicAdd(&g_colsum[c0 + j], s);
        }
        __syncthreads();
        red[t] = csq[j];
        __syncthreads();
        if (ty == 0) {
            float s = 0.f;
            #pragma unroll
            for (int yy = 0; yy < 16; yy++) s += red[yy * 16 + tx];
            atomicAdd(&g_colsq[c0 + j], s);
        }
        __syncthreads();
    }
}

// ---------------- K_post: fold c2 terms into column stats ----------------
// stats of y=z+c2[batch]: colsum += sum_g cnt*c2 ; colsq += sum_g (2*zsum*c2 + cnt*c2^2)
__global__ void k_post() {
    int c = threadIdx.x;           // 128
    int g0 = blockIdx.x * (NG / 16);
    float s = 0.f, q = 0.f;
    for (int g = g0; g < g0 + NG / 16; g++) {
        float cnt = g_cnt[g];
        float c2  = g_c2[g * FD + c];
        float zs  = g_zsum[g * FD + c];
        s += cnt * c2;
        q += 2.f * zs * c2 + cnt * c2 * c2;
    }
    atomicAdd(&g_colsum[c], s);
    atomicAdd(&g_colsq[c], q);
}

// ---------------- K5b: finalize BN scale/shift ----------------
__global__ void k_fin(const float* __restrict__ bng, const float* __restrict__ bnb) {
    int c = threadIdx.x;
    float mu  = g_colsum[c] / (float)NN;
    float var = g_colsq[c] / (float)NN - mu * mu;
    float inv = rsqrtf(var + EPSV);
    float sc  = bng[c] * inv;
    g_scale[c] = sc;
    g_shift[c] = bnb[c] - mu * sc;
}

// ---------------- K6: out = x + (z + c2[batch]) * scale + shift --------------
__global__ void k_out(const float* __restrict__ x, const int* __restrict__ batch,
                      float* __restrict__ out) {
    int idx = blockIdx.x * blockDim.x + threadIdx.x;
    if (idx >= NN * 32) return;
    int n = idx >> 5;
    int qd = idx & 31;
    int c0 = qd << 2;
    int g = batch[n];
    float4 zvv = *(const float4*)(g_z + (size_t)n * FD + c0);
    float4 xv = *(const float4*)(x + (size_t)n * FD + c0);
    float4 cv = *(const float4*)(g_c2 + g * FD + c0);
    float4 sc = *(const float4*)(g_scale + c0);
    float4 sh = *(const float4*)(g_shift + c0);
    float4 o;
    o.x = xv.x + (zvv.x + cv.x) * sc.x + sh.x;
    o.y = xv.y + (zvv.y + cv.y) * sc.y + sh.y;
    o.z = xv.z + (zvv.z + cv.z) * sc.z + sh.z;
    o.w = xv.w + (zvv.w + cv.w) * sc.w + sh.w;
    ((float4*)out)[idx] = o;
}

// ---------------- host ----------------
extern "C" void kernel_launch(void* const* d_in, const int* in_sizes, int n_in,
                              void* d_out, int out_size) {
    const float* x     = (const float*)d_in[0];
    const int*   batch = (const int*)d_in[1];
    const float* pers0 = (const float*)d_in[2];
    const float* g1w   = (const float*)d_in[3];
    const float* g1b   = (const float*)d_in[4];
    const float* l1w   = (const float*)d_in[5];
    const float* g2w   = (const float*)d_in[6];
    const float* g2b   = (const float*)d_in[7];
    const float* l2w   = (const float*)d_in[8];
    const float* bng   = (const float*)d_in[9];
    const float* bnb   = (const float*)d_in[10];
    float* out = (float*)d_out;

    int sms = 148;
    cudaDeviceGetAttribute(&sms, cudaDevAttrMultiProcessorCount, 0);

    const int smem_main  = (IN0 * WST + FD * WST + TM * XST) * 4 + TM * 4;  // 219,904 B
    const int smem_corr1 = (FD * 145 + IN0) * 4;
    const int smem_corr2 = (FD * 129 + FD) * 4;
    cudaFuncSetAttribute(k_main, cudaFuncAttributeMaxDynamicSharedMemorySize, smem_main);
    cudaFuncSetAttribute(k_corr, cudaFuncAttributeMaxDynamicSharedMemorySize, smem_corr1);

    k_init<<<(NG * FD + 255) / 256, 256>>>();
    k_tr<<<(NN + 31) / 32, 256>>>((const float2*)pers0);
    k_bounds<<<(NN + 255) / 256, 256>>>(batch);
    k_segsum<<<NG, 384>>>(x);
    k_corr<<<NG / 16, 128, smem_corr1>>>(0, l1w, g1b, IN0, 145);
    k_main<<<sms, 256, smem_main>>>(x, batch, g1w, g2w);
    k_corr<<<NG / 16, 128, smem_corr2>>>(1, l2w, g2b, FD, 129);
    k_post<<<16, 128>>>();
    k_fin<<<1, 128>>>(bng, bnb);
    k_out<<<(NN * 32 + 255) / 256, 256>>>(x, batch, out);
}